// round 10
// baseline (speedup 1.0000x reference)
#include <cuda_runtime.h>
#include <cuda_bf16.h>
#include <cstdint>

// ---------------------------------------------------------------------------
// RNN: h_t = tanh(x_t @ Wx + h_{t-1} @ Wh),  B=32, L=512, D=1024, fp32.
// Phase 1: xp = x @ Wx via mma.sync 3xTF32; splits hoisted to staging (SMEM
//          holds pre-split hi/lo tf32 tiles).
// Phase 2: persistent recurrence (R5 design: 256 thr, Wh in regs, 4 group
//          barriers, xp prefetch).
// ---------------------------------------------------------------------------

#define B_DIM 32
#define L_DIM 512
#define D_DIM 1024
#define NB 128
#define TPB 256

typedef unsigned long long u64;

__device__ unsigned g_ctrs[4];

__global__ void init_flags_kernel() {
    if (threadIdx.x < 4) g_ctrs[threadIdx.x] = 0u;
}

__device__ __forceinline__ u64 pack2(float lo, float hi) {
    u64 r;
    asm("mov.b64 %0, {%1, %2};" : "=l"(r) : "f"(lo), "f"(hi));
    return r;
}
__device__ __forceinline__ void unpack2(u64 v, float& lo, float& hi) {
    asm("mov.b64 {%0, %1}, %2;" : "=f"(lo), "=f"(hi) : "l"(v));
}
__device__ __forceinline__ void ffma2(u64& d, u64 a, u64 b) {
    asm("fma.rn.f32x2 %0, %1, %2, %0;" : "+l"(d) : "l"(a), "l"(b));
}

// tf32 split: hi = tf32(v), lo = tf32(v - float(hi))
__device__ __forceinline__ void tf32_split(float v, uint32_t& hi, uint32_t& lo) {
    asm("cvt.rna.tf32.f32 %0, %1;" : "=r"(hi) : "f"(v));
    float r = v - __uint_as_float(hi);
    asm("cvt.rna.tf32.f32 %0, %1;" : "=r"(lo) : "f"(r));
}

__device__ __forceinline__ void mma_tf32(float* d, const uint32_t* a, const uint32_t* b) {
    asm("mma.sync.aligned.m16n8k8.row.col.f32.tf32.tf32.f32 "
        "{%0,%1,%2,%3}, {%4,%5,%6,%7}, {%8,%9}, {%0,%1,%2,%3};"
        : "+f"(d[0]), "+f"(d[1]), "+f"(d[2]), "+f"(d[3])
        : "r"(a[0]), "r"(a[1]), "r"(a[2]), "r"(a[3]), "r"(b[0]), "r"(b[1]));
}

// ---------------------------------------------------------------------------
// Phase 1: C[16384,1024] = A[16384,1024] * W[1024,1024], 3xTF32 mma.sync.
// Block tile 128x128, 8 warps (2 x 4), warp tile 64x32, K-tile 32.
// SMEM holds PRE-SPLIT tiles: A_hi, A_lo (rows=m, cols=k) and B_hi, B_lo
// (rows=n, cols=k), double-buffered. MMA loop = pure LDS + HMMA.
// ---------------------------------------------------------------------------
#define KT 32
#define AST 36                           // u32 per row in SMEM tiles
#define TILE_U32 (128 * AST)             // one component tile
#define BUF_STRIDE (4 * TILE_U32)        // Ah, Al, Bh, Bl
#define P1_SMEM_BYTES (2 * BUF_STRIDE * 4)

__global__ __launch_bounds__(256, 1) void gemm_mma_kernel(
    const float* __restrict__ A, const float* __restrict__ W,
    float* __restrict__ C)
{
    extern __shared__ __align__(16) uint32_t smu[];
    // per buffer: [Ah][Al][Bh][Bl], each 128*AST u32

    const int tid  = threadIdx.x;
    const int warp = tid >> 5;
    const int lane = tid & 31;
    const int wm = warp >> 2;        // 0..1  -> m offset wm*64
    const int wn = warp & 3;         // 0..3  -> n offset wn*32
    const int m0 = blockIdx.y * 128;
    const int n0 = blockIdx.x * 128;

    const int lr = lane >> 2;        // 0..7
    const int lc = lane & 3;         // 0..3

    // staging indices
    const int saR = tid >> 3, saK4 = tid & 7;          // A: per-it base uses idx
    (void)saR; (void)saK4;

    float acc[4][4][4];
#pragma unroll
    for (int i = 0; i < 4; ++i)
#pragma unroll
        for (int j = 0; j < 4; ++j)
#pragma unroll
            for (int p = 0; p < 4; ++p) acc[i][j][p] = 0.0f;

    // ---- staging helpers (split + store) ----
    auto stageA = [&](uint32_t* buf, int it, float4 v) {
        int idx = it * 256 + tid;
        int r = idx >> 3, k4 = idx & 7;
        uint4 hv, lv;
        tf32_split(v.x, hv.x, lv.x);
        tf32_split(v.y, hv.y, lv.y);
        tf32_split(v.z, hv.z, lv.z);
        tf32_split(v.w, hv.w, lv.w);
        *(uint4*)(buf + r * AST + k4 * 4) = hv;                 // Ah
        *(uint4*)(buf + TILE_U32 + r * AST + k4 * 4) = lv;      // Al
    };
    auto stageB = [&](uint32_t* buf, int it, float4 v) {
        int idx = it * 256 + tid;
        int kr = idx >> 5, n4 = idx & 31;
        uint32_t* bh = buf + 2 * TILE_U32 + kr;
        uint32_t* bl = buf + 3 * TILE_U32 + kr;
        uint32_t h, l;
        tf32_split(v.x, h, l); bh[(n4 * 4 + 0) * AST] = h; bl[(n4 * 4 + 0) * AST] = l;
        tf32_split(v.y, h, l); bh[(n4 * 4 + 1) * AST] = h; bl[(n4 * 4 + 1) * AST] = l;
        tf32_split(v.z, h, l); bh[(n4 * 4 + 2) * AST] = h; bl[(n4 * 4 + 2) * AST] = l;
        tf32_split(v.w, h, l); bh[(n4 * 4 + 3) * AST] = h; bl[(n4 * 4 + 3) * AST] = l;
    };

    // prologue: tile 0 into buffer 0
    {
        uint32_t* buf = smu;
#pragma unroll
        for (int it = 0; it < 4; ++it) {
            int idx = it * 256 + tid;
            int r = idx >> 3, k4 = idx & 7;
            float4 v = __ldg((const float4*)(A + (size_t)(m0 + r) * D_DIM + k4 * 4));
            stageA(buf, it, v);
        }
#pragma unroll
        for (int it = 0; it < 4; ++it) {
            int idx = it * 256 + tid;
            int kr = idx >> 5, n4 = idx & 31;
            float4 v = __ldg((const float4*)(W + (size_t)kr * D_DIM + n0 + n4 * 4));
            stageB(buf, it, v);
        }
    }
    __syncthreads();

    int cur = 0;
    for (int kt = 0; kt < D_DIM / KT; ++kt) {
        // prefetch next tile into registers (raw fp32)
        float4 va[4], vb[4];
        const bool more = (kt + 1) < (D_DIM / KT);
        if (more) {
            const int k0n = (kt + 1) * KT;
#pragma unroll
            for (int it = 0; it < 4; ++it) {
                int idx = it * 256 + tid;
                int r = idx >> 3, k4 = idx & 7;
                va[it] = __ldg((const float4*)(A + (size_t)(m0 + r) * D_DIM + k0n + k4 * 4));
            }
#pragma unroll
            for (int it = 0; it < 4; ++it) {
                int idx = it * 256 + tid;
                int kr = idx >> 5, n4 = idx & 31;
                vb[it] = __ldg((const float4*)(W + (size_t)(k0n + kr) * D_DIM + n0 + n4 * 4));
            }
        }

        // compute on buffer cur: pure LDS + HMMA
        const uint32_t* ah_t = smu + cur * BUF_STRIDE;
        const uint32_t* al_t = ah_t + TILE_U32;
        const uint32_t* bh_t = ah_t + 2 * TILE_U32;
        const uint32_t* bl_t = ah_t + 3 * TILE_U32;
#pragma unroll
        for (int ks = 0; ks < 4; ++ks) {
            const int kbase = ks * 8;
            uint32_t ah[4][4], al[4][4];
#pragma unroll
            for (int fm = 0; fm < 4; ++fm) {
                const int rb = (wm * 64 + fm * 16 + lr) * AST + kbase + lc;
                ah[fm][0] = ah_t[rb];
                ah[fm][1] = ah_t[rb + 8 * AST];
                ah[fm][2] = ah_t[rb + 4];
                ah[fm][3] = ah_t[rb + 8 * AST + 4];
                al[fm][0] = al_t[rb];
                al[fm][1] = al_t[rb + 8 * AST];
                al[fm][2] = al_t[rb + 4];
                al[fm][3] = al_t[rb + 8 * AST + 4];
            }
            uint32_t bh[4][2], bl[4][2];
#pragma unroll
            for (int fn = 0; fn < 4; ++fn) {
                const int nb = (wn * 32 + fn * 8 + lr) * AST + kbase + lc;
                bh[fn][0] = bh_t[nb];
                bh[fn][1] = bh_t[nb + 4];
                bl[fn][0] = bl_t[nb];
                bl[fn][1] = bl_t[nb + 4];
            }
#pragma unroll
            for (int fm = 0; fm < 4; ++fm)
#pragma unroll
                for (int fn = 0; fn < 4; ++fn) {
                    mma_tf32(acc[fm][fn], ah[fm], bl[fn]);
                    mma_tf32(acc[fm][fn], al[fm], bh[fn]);
                    mma_tf32(acc[fm][fn], ah[fm], bh[fn]);
                }
        }

        if (more) {
            uint32_t* buf = smu + (cur ^ 1) * BUF_STRIDE;
#pragma unroll
            for (int it = 0; it < 4; ++it) stageA(buf, it, va[it]);
#pragma unroll
            for (int it = 0; it < 4; ++it) stageB(buf, it, vb[it]);
            __syncthreads();
        }
        cur ^= 1;
    }

    // epilogue: store accumulators (float2 per frag-row)
#pragma unroll
    for (int fm = 0; fm < 4; ++fm) {
        const int rbase = m0 + wm * 64 + fm * 16 + lr;
#pragma unroll
        for (int fn = 0; fn < 4; ++fn) {
            const int cbase = n0 + wn * 32 + fn * 8 + lc * 2;
            *(float2*)(C + (size_t)rbase * D_DIM + cbase) =
                make_float2(acc[fm][fn][0], acc[fm][fn][1]);
            *(float2*)(C + (size_t)(rbase + 8) * D_DIM + cbase) =
                make_float2(acc[fm][fn][2], acc[fm][fn][3]);
        }
    }
}

// ---------------------------------------------------------------------------
// Phase 2: persistent recurrence (R5 design, 256 threads).
// bid -> (bq = bid>>5 owns b in [bq*8, bq*8+8), jg = bid&31 owns 32 columns).
// Thread: jq = lane&7 -> 4 columns; kc = warp*4 + (lane>>3) -> 32 k.
// ---------------------------------------------------------------------------
#define HROW_F 1152
#define PART_STRIDE 36
#define HS_FLOATS (8 * HROW_F)
#define PART_OFF HS_FLOATS
#define PART_FLOATS (8 * 32 * PART_STRIDE)
#define SMEM2_FLOATS (PART_OFF + PART_FLOATS)

__global__ __launch_bounds__(TPB, 1) void rnn_steps_kernel(
    float* __restrict__ out,          // [B, L, D]: holds xp, overwritten by h
    const float* __restrict__ h0,     // [B, D]
    const float* __restrict__ Wh)     // [D, D]
{
    extern __shared__ __align__(16) float smem[];
    float* hs   = smem;
    float* part = smem + PART_OFF;

    const int tid  = threadIdx.x;
    const int warp = tid >> 5;
    const int lane = tid & 31;
    const int bid  = blockIdx.x;
    const int jg = bid & 31, bq = bid >> 5;
    const int j0 = jg * 32, b0 = bq * 8;
    const int jq = lane & 7;
    const int kc = (warp << 2) | (lane >> 3);
    const int kb = kc * 32;

    u64 wreg[4][16];
#pragma unroll
    for (int jl = 0; jl < 4; ++jl) {
        const int jcol = j0 + jq * 4 + jl;
#pragma unroll
        for (int kk = 0; kk < 16; ++kk) {
            float w0 = Wh[(size_t)(kb + 2 * kk)     * D_DIM + jcol];
            float w1 = Wh[(size_t)(kb + 2 * kk + 1) * D_DIM + jcol];
            wreg[jl][kk] = pack2(w0, w1);
        }
    }

    unsigned* ctr = &g_ctrs[bq];
    const size_t obase = ((size_t)(b0 + warp) * L_DIM) * D_DIM + j0 + lane;

    float xp = out[obase];

    for (int t = 0; t < L_DIM; ++t) {
        const size_t orow = obase + (size_t)t * D_DIM;

        const float* src = (t == 0)
            ? (h0 + (size_t)(b0 + warp) * D_DIM)
            : (out + ((size_t)(b0 + warp) * L_DIM + (t - 1)) * D_DIM);
#pragma unroll
        for (int half = 0; half < 2; ++half) {
            float4 v[4];
#pragma unroll
            for (int m = 0; m < 4; ++m)
                v[m] = __ldcg((const float4*)(src + ((half * 4 + m) * 32 + lane) * 4));
#pragma unroll
            for (int m = 0; m < 4; ++m) {
                int idx = (half * 4 + m) * 32 + lane;
                *(float4*)(hs + warp * HROW_F + (idx >> 3) * 36 + (idx & 7) * 4) = v[m];
            }
        }
        __syncthreads();

        u64 acc[8][4];
#pragma unroll
        for (int b = 0; b < 8; ++b)
#pragma unroll
            for (int jl = 0; jl < 4; ++jl) acc[b][jl] = 0ull;

#pragma unroll
        for (int b = 0; b < 8; ++b) {
            const ulonglong2* hb = (const ulonglong2*)(hs + b * HROW_F + kc * 36);
#pragma unroll
            for (int i = 0; i < 8; ++i) {
                ulonglong2 hp = hb[i];
                ffma2(acc[b][0], hp.x, wreg[0][2 * i]);
                ffma2(acc[b][1], hp.x, wreg[1][2 * i]);
                ffma2(acc[b][2], hp.x, wreg[2][2 * i]);
                ffma2(acc[b][3], hp.x, wreg[3][2 * i]);
                ffma2(acc[b][0], hp.y, wreg[0][2 * i + 1]);
                ffma2(acc[b][1], hp.y, wreg[1][2 * i + 1]);
                ffma2(acc[b][2], hp.y, wreg[2][2 * i + 1]);
                ffma2(acc[b][3], hp.y, wreg[3][2 * i + 1]);
            }
        }

#pragma unroll
        for (int b = 0; b < 8; ++b)
#pragma unroll
            for (int jl = 0; jl < 4; ++jl) {
                float lo, hi;
                unpack2(acc[b][jl], lo, hi);
                part[(b * 32 + jq * 4 + jl) * PART_STRIDE + kc] = lo + hi;
            }

        float xp_next = 0.0f;
        if (t + 1 < L_DIM) xp_next = out[orow + D_DIM];

        __syncthreads();

        float s = xp;
        const float* pr = part + (warp * 32 + lane) * PART_STRIDE;
#pragma unroll
        for (int g = 0; g < 8; ++g) {
            float4 p = *(const float4*)(pr + g * 4);
            s += (p.x + p.y) + (p.z + p.w);
        }
        out[orow] = tanhf(s);

        __syncthreads();
        if (tid == 0) {
            asm volatile("red.release.gpu.add.u32 [%0], 1;" :: "l"(ctr) : "memory");
            const unsigned target = 32u * (unsigned)(t + 1);
            unsigned v;
            int spins = 0;
            while (true) {
                asm volatile("ld.acquire.gpu.u32 %0, [%1];" : "=r"(v) : "l"(ctr) : "memory");
                if (v >= target) break;
                if (++spins > 2) __nanosleep(32);
            }
        }
        __syncthreads();

        xp = xp_next;
    }
}

// ---------------------------------------------------------------------------
extern "C" void kernel_launch(void* const* d_in, const int* in_sizes, int n_in,
                              void* d_out, int out_size)
{
    (void)in_sizes; (void)n_in; (void)out_size;
    const float* x  = (const float*)d_in[0];
    const float* h0 = (const float*)d_in[1];
    const float* Wx = (const float*)d_in[2];
    const float* Wh = (const float*)d_in[3];
    float* out = (float*)d_out;

    // phase 1: 3xTF32 tensor-core GEMM (pre-split staging)
    cudaFuncSetAttribute(gemm_mma_kernel,
                         cudaFuncAttributeMaxDynamicSharedMemorySize,
                         P1_SMEM_BYTES);
    dim3 g1(D_DIM / 128, (B_DIM * L_DIM) / 128);
    gemm_mma_kernel<<<g1, 256, P1_SMEM_BYTES>>>(x, Wx, out);

    // phase 2: persistent recurrence
    init_flags_kernel<<<1, 32>>>();
    size_t smem_bytes = (size_t)SMEM2_FLOATS * sizeof(float);
    cudaFuncSetAttribute(rnn_steps_kernel,
                         cudaFuncAttributeMaxDynamicSharedMemorySize,
                         (int)smem_bytes);
    rnn_steps_kernel<<<NB, TPB, smem_bytes>>>(out, h0, Wh);
}

// round 11
// speedup vs baseline: 1.1245x; 1.1245x over previous
#include <cuda_runtime.h>
#include <cuda_bf16.h>
#include <cstdint>

// ---------------------------------------------------------------------------
// RNN: h_t = tanh(x_t @ Wx + h_{t-1} @ Wh),  B=32, L=512, D=1024, fp32.
// Phase 1: xp = x @ Wx via mma.sync 3xTF32 (hi/lo split in-loop; R9 version).
// Phase 2: persistent recurrence (R5 design + XOR-swizzled partial STS,
//          early xp prefetch, no final barrier).
// ---------------------------------------------------------------------------

#define B_DIM 32
#define L_DIM 512
#define D_DIM 1024
#define NB 128
#define TPB 256

typedef unsigned long long u64;

__device__ unsigned g_ctrs[4];

__global__ void init_flags_kernel() {
    if (threadIdx.x < 4) g_ctrs[threadIdx.x] = 0u;
}

__device__ __forceinline__ u64 pack2(float lo, float hi) {
    u64 r;
    asm("mov.b64 %0, {%1, %2};" : "=l"(r) : "f"(lo), "f"(hi));
    return r;
}
__device__ __forceinline__ void unpack2(u64 v, float& lo, float& hi) {
    asm("mov.b64 {%0, %1}, %2;" : "=f"(lo), "=f"(hi) : "l"(v));
}
__device__ __forceinline__ void ffma2(u64& d, u64 a, u64 b) {
    asm("fma.rn.f32x2 %0, %1, %2, %0;" : "+l"(d) : "l"(a), "l"(b));
}

// tf32 split: hi = tf32(v), lo = tf32(v - float(hi))
__device__ __forceinline__ void tf32_split(float v, uint32_t& hi, uint32_t& lo) {
    asm("cvt.rna.tf32.f32 %0, %1;" : "=r"(hi) : "f"(v));
    float r = v - __uint_as_float(hi);
    asm("cvt.rna.tf32.f32 %0, %1;" : "=r"(lo) : "f"(r));
}

__device__ __forceinline__ void mma_tf32(float* d, const uint32_t* a, const uint32_t* b) {
    asm("mma.sync.aligned.m16n8k8.row.col.f32.tf32.tf32.f32 "
        "{%0,%1,%2,%3}, {%4,%5,%6,%7}, {%8,%9}, {%0,%1,%2,%3};"
        : "+f"(d[0]), "+f"(d[1]), "+f"(d[2]), "+f"(d[3])
        : "r"(a[0]), "r"(a[1]), "r"(a[2]), "r"(a[3]), "r"(b[0]), "r"(b[1]));
}

// ---------------------------------------------------------------------------
// Phase 1: C[16384,1024] = A[16384,1024] * W[1024,1024], 3xTF32 mma.sync.
// Block tile 128x128, 8 warps (2 x 4), warp tile 64x32, K-tile 32,
// double-buffered fp32 SMEM (stride 36), register prefetch. (R9 version.)
// ---------------------------------------------------------------------------
#define KT 32
#define AST 36                         // floats per row in SMEM tiles
#define BUF_F (128 * AST)              // one tile buffer (A or B)
#define P1_SMEM_BYTES (4 * BUF_F * 4)  // A0,A1,B0,B1

__global__ __launch_bounds__(256, 1) void gemm_mma_kernel(
    const float* __restrict__ A, const float* __restrict__ W,
    float* __restrict__ C)
{
    extern __shared__ __align__(16) float sm1[];
    float* As = sm1;                 // [2][128*36]  rows = m, cols = k
    float* Bs = sm1 + 2 * BUF_F;     // [2][128*36]  rows = n, cols = k

    const int tid  = threadIdx.x;
    const int warp = tid >> 5;
    const int lane = tid & 31;
    const int wm = warp >> 2;        // 0..1  -> m offset wm*64
    const int wn = warp & 3;         // 0..3  -> n offset wn*32
    const int m0 = blockIdx.y * 128;
    const int n0 = blockIdx.x * 128;

    const int lr = lane >> 2;        // 0..7
    const int lc = lane & 3;         // 0..3

    float acc[4][4][4];
#pragma unroll
    for (int i = 0; i < 4; ++i)
#pragma unroll
        for (int j = 0; j < 4; ++j)
#pragma unroll
            for (int p = 0; p < 4; ++p) acc[i][j][p] = 0.0f;

    // prologue: tile 0 into buffer 0
    {
#pragma unroll
        for (int it = 0; it < 4; ++it) {
            int idx = it * 256 + tid;
            int r = idx >> 3, k4 = idx & 7;
            float4 v = __ldg((const float4*)(A + (size_t)(m0 + r) * D_DIM + k4 * 4));
            *(float4*)(As + r * AST + k4 * 4) = v;
        }
#pragma unroll
        for (int it = 0; it < 4; ++it) {
            int idx = it * 256 + tid;
            int kr = idx >> 5, n4 = idx & 31;
            float4 v = __ldg((const float4*)(W + (size_t)kr * D_DIM + n0 + n4 * 4));
            float* bp = Bs + kr;
            bp[(n4 * 4 + 0) * AST] = v.x;
            bp[(n4 * 4 + 1) * AST] = v.y;
            bp[(n4 * 4 + 2) * AST] = v.z;
            bp[(n4 * 4 + 3) * AST] = v.w;
        }
    }
    __syncthreads();

    int cur = 0;
    for (int kt = 0; kt < D_DIM / KT; ++kt) {
        // prefetch next tile into registers
        float4 va[4], vb[4];
        const bool more = (kt + 1) < (D_DIM / KT);
        if (more) {
            const int k0n = (kt + 1) * KT;
#pragma unroll
            for (int it = 0; it < 4; ++it) {
                int idx = it * 256 + tid;
                int r = idx >> 3, k4 = idx & 7;
                va[it] = __ldg((const float4*)(A + (size_t)(m0 + r) * D_DIM + k0n + k4 * 4));
            }
#pragma unroll
            for (int it = 0; it < 4; ++it) {
                int idx = it * 256 + tid;
                int kr = idx >> 5, n4 = idx & 31;
                vb[it] = __ldg((const float4*)(W + (size_t)(k0n + kr) * D_DIM + n0 + n4 * 4));
            }
        }

        // compute on buffer cur
        const float* as = As + cur * BUF_F;
        const float* bs = Bs + cur * BUF_F;
#pragma unroll
        for (int ks = 0; ks < 4; ++ks) {
            const int kbase = ks * 8;
            uint32_t ah[4][4], al[4][4];
#pragma unroll
            for (int fm = 0; fm < 4; ++fm) {
                const int rbase = wm * 64 + fm * 16;
                float a0 = as[(rbase + lr) * AST + kbase + lc];
                float a1 = as[(rbase + lr + 8) * AST + kbase + lc];
                float a2 = as[(rbase + lr) * AST + kbase + lc + 4];
                float a3 = as[(rbase + lr + 8) * AST + kbase + lc + 4];
                tf32_split(a0, ah[fm][0], al[fm][0]);
                tf32_split(a1, ah[fm][1], al[fm][1]);
                tf32_split(a2, ah[fm][2], al[fm][2]);
                tf32_split(a3, ah[fm][3], al[fm][3]);
            }
            uint32_t bh[4][2], bl[4][2];
#pragma unroll
            for (int fn = 0; fn < 4; ++fn) {
                const int nbase = wn * 32 + fn * 8;
                float b0 = bs[(nbase + lr) * AST + kbase + lc];
                float b1 = bs[(nbase + lr) * AST + kbase + lc + 4];
                tf32_split(b0, bh[fn][0], bl[fn][0]);
                tf32_split(b1, bh[fn][1], bl[fn][1]);
            }
#pragma unroll
            for (int fm = 0; fm < 4; ++fm)
#pragma unroll
                for (int fn = 0; fn < 4; ++fn) {
                    mma_tf32(acc[fm][fn], ah[fm], bl[fn]);
                    mma_tf32(acc[fm][fn], al[fm], bh[fn]);
                    mma_tf32(acc[fm][fn], ah[fm], bh[fn]);
                }
        }

        if (more) {
            float* asn = As + (cur ^ 1) * BUF_F;
            float* bsn = Bs + (cur ^ 1) * BUF_F;
#pragma unroll
            for (int it = 0; it < 4; ++it) {
                int idx = it * 256 + tid;
                int r = idx >> 3, k4 = idx & 7;
                *(float4*)(asn + r * AST + k4 * 4) = va[it];
            }
#pragma unroll
            for (int it = 0; it < 4; ++it) {
                int idx = it * 256 + tid;
                int kr = idx >> 5, n4 = idx & 31;
                float* bp = bsn + kr;
                bp[(n4 * 4 + 0) * AST] = vb[it].x;
                bp[(n4 * 4 + 1) * AST] = vb[it].y;
                bp[(n4 * 4 + 2) * AST] = vb[it].z;
                bp[(n4 * 4 + 3) * AST] = vb[it].w;
            }
            __syncthreads();
        }
        cur ^= 1;
    }

    // epilogue: store accumulators (float2 per frag-row)
#pragma unroll
    for (int fm = 0; fm < 4; ++fm) {
        const int rbase = m0 + wm * 64 + fm * 16 + lr;
#pragma unroll
        for (int fn = 0; fn < 4; ++fn) {
            const int cbase = n0 + wn * 32 + fn * 8 + lc * 2;
            *(float2*)(C + (size_t)rbase * D_DIM + cbase) =
                make_float2(acc[fm][fn][0], acc[fm][fn][1]);
            *(float2*)(C + (size_t)(rbase + 8) * D_DIM + cbase) =
                make_float2(acc[fm][fn][2], acc[fm][fn][3]);
        }
    }
}

// ---------------------------------------------------------------------------
// Phase 2: persistent recurrence (256 threads).
// bid -> (bq = bid>>5 owns b in [bq*8, bq*8+8), jg = bid&31 owns 32 columns).
// Thread: jq = lane&7 -> 4 columns; kc = warp*4 + (lane>>3) -> 32 k.
// Partial STS uses column swizzle col' = kc ^ (jq<<2): per-STS banks
// 16(jq&1) + 4(warp^jq) + s -> all 32 distinct (conflict-free). Reducer sums
// all 32 columns of its row (permutation-invariant), code unchanged.
// ---------------------------------------------------------------------------
#define HROW_F 1152
#define PART_STRIDE 36
#define HS_FLOATS (8 * HROW_F)
#define PART_OFF HS_FLOATS
#define PART_FLOATS (8 * 32 * PART_STRIDE)
#define SMEM2_FLOATS (PART_OFF + PART_FLOATS)

__global__ __launch_bounds__(TPB, 1) void rnn_steps_kernel(
    float* __restrict__ out,          // [B, L, D]: holds xp, overwritten by h
    const float* __restrict__ h0,     // [B, D]
    const float* __restrict__ Wh)     // [D, D]
{
    extern __shared__ __align__(16) float smem[];
    float* hs   = smem;
    float* part = smem + PART_OFF;

    const int tid  = threadIdx.x;
    const int warp = tid >> 5;
    const int lane = tid & 31;
    const int bid  = blockIdx.x;
    const int jg = bid & 31, bq = bid >> 5;
    const int j0 = jg * 32, b0 = bq * 8;
    const int jq = lane & 7;
    const int kc = (warp << 2) | (lane >> 3);
    const int kb = kc * 32;
    const int kcs = kc ^ (jq << 2);            // swizzled partial column

    u64 wreg[4][16];
#pragma unroll
    for (int jl = 0; jl < 4; ++jl) {
        const int jcol = j0 + jq * 4 + jl;
#pragma unroll
        for (int kk = 0; kk < 16; ++kk) {
            float w0 = Wh[(size_t)(kb + 2 * kk)     * D_DIM + jcol];
            float w1 = Wh[(size_t)(kb + 2 * kk + 1) * D_DIM + jcol];
            wreg[jl][kk] = pack2(w0, w1);
        }
    }

    unsigned* ctr = &g_ctrs[bq];
    const size_t obase = ((size_t)(b0 + warp) * L_DIM) * D_DIM + j0 + lane;

    float xp = out[obase];

    for (int t = 0; t < L_DIM; ++t) {
        const size_t orow = obase + (size_t)t * D_DIM;

        const float* src = (t == 0)
            ? (h0 + (size_t)(b0 + warp) * D_DIM)
            : (out + ((size_t)(b0 + warp) * L_DIM + (t - 1)) * D_DIM);
#pragma unroll
        for (int half = 0; half < 2; ++half) {
            float4 v[4];
#pragma unroll
            for (int m = 0; m < 4; ++m)
                v[m] = __ldcg((const float4*)(src + ((half * 4 + m) * 32 + lane) * 4));
#pragma unroll
            for (int m = 0; m < 4; ++m) {
                int idx = (half * 4 + m) * 32 + lane;
                *(float4*)(hs + warp * HROW_F + (idx >> 3) * 36 + (idx & 7) * 4) = v[m];
            }
        }
        __syncthreads();

        // early xp prefetch for t+1: slot written only by this thread at t+1.
        float xp_next = 0.0f;
        if (t + 1 < L_DIM) xp_next = out[orow + D_DIM];

        u64 acc[8][4];
#pragma unroll
        for (int b = 0; b < 8; ++b)
#pragma unroll
            for (int jl = 0; jl < 4; ++jl) acc[b][jl] = 0ull;

#pragma unroll
        for (int b = 0; b < 8; ++b) {
            const ulonglong2* hb = (const ulonglong2*)(hs + b * HROW_F + kc * 36);
#pragma unroll
            for (int i = 0; i < 8; ++i) {
                ulonglong2 hp = hb[i];
                ffma2(acc[b][0], hp.x, wreg[0][2 * i]);
                ffma2(acc[b][1], hp.x, wreg[1][2 * i]);
                ffma2(acc[b][2], hp.x, wreg[2][2 * i]);
                ffma2(acc[b][3], hp.x, wreg[3][2 * i]);
                ffma2(acc[b][0], hp.y, wreg[0][2 * i + 1]);
                ffma2(acc[b][1], hp.y, wreg[1][2 * i + 1]);
                ffma2(acc[b][2], hp.y, wreg[2][2 * i + 1]);
                ffma2(acc[b][3], hp.y, wreg[3][2 * i + 1]);
            }
        }

#pragma unroll
        for (int b = 0; b < 8; ++b)
#pragma unroll
            for (int jl = 0; jl < 4; ++jl) {
                float lo, hi;
                unpack2(acc[b][jl], lo, hi);
                part[(b * 32 + jq * 4 + jl) * PART_STRIDE + kcs] = lo + hi;
            }

        __syncthreads();

        float s = xp;
        const float* pr = part + (warp * 32 + lane) * PART_STRIDE;
#pragma unroll
        for (int g = 0; g < 8; ++g) {
            float4 p = *(const float4*)(pr + g * 4);
            s += (p.x + p.y) + (p.z + p.w);
        }
        out[orow] = tanhf(s);

        if (t + 1 < L_DIM) {
            __syncthreads();   // all STG issued; also protects hs/part reuse
            if (tid == 0) {
                asm volatile("red.release.gpu.add.u32 [%0], 1;" :: "l"(ctr) : "memory");
                const unsigned target = 32u * (unsigned)(t + 1);
                unsigned v;
                int spins = 0;
                while (true) {
                    asm volatile("ld.acquire.gpu.u32 %0, [%1];" : "=r"(v) : "l"(ctr) : "memory");
                    if (v >= target) break;
                    if (++spins > 2) __nanosleep(32);
                }
            }
            __syncthreads();
        }

        xp = xp_next;
    }
}

// ---------------------------------------------------------------------------
extern "C" void kernel_launch(void* const* d_in, const int* in_sizes, int n_in,
                              void* d_out, int out_size)
{
    (void)in_sizes; (void)n_in; (void)out_size;
    const float* x  = (const float*)d_in[0];
    const float* h0 = (const float*)d_in[1];
    const float* Wx = (const float*)d_in[2];
    const float* Wh = (const float*)d_in[3];
    float* out = (float*)d_out;

    // phase 1: 3xTF32 tensor-core GEMM
    cudaFuncSetAttribute(gemm_mma_kernel,
                         cudaFuncAttributeMaxDynamicSharedMemorySize,
                         P1_SMEM_BYTES);
    dim3 g1(D_DIM / 128, (B_DIM * L_DIM) / 128);
    gemm_mma_kernel<<<g1, 256, P1_SMEM_BYTES>>>(x, Wx, out);

    // phase 2: persistent recurrence
    init_flags_kernel<<<1, 32>>>();
    size_t smem_bytes = (size_t)SMEM2_FLOATS * sizeof(float);
    cudaFuncSetAttribute(rnn_steps_kernel,
                         cudaFuncAttributeMaxDynamicSharedMemorySize,
                         (int)smem_bytes);
    rnn_steps_kernel<<<NB, TPB, smem_bytes>>>(out, h0, Wh);
}

// round 12
// speedup vs baseline: 1.2448x; 1.1070x over previous
#include <cuda_runtime.h>
#include <cuda_bf16.h>
#include <cstdint>

// ---------------------------------------------------------------------------
// RNN: h_t = tanh(x_t @ Wx + h_{t-1} @ Wh),  B=32, L=512, D=1024, fp32.
// Phase 1: xp = x @ Wx via mma.sync 3xTF32, cp.async double-buffered staging,
//          B stored k-major (BST=136, conflict-free), 2 CTAs/SM.
// Phase 2: persistent recurrence (R11: swizzled partials, early xp prefetch,
//          4 group barriers, no final barrier).
// ---------------------------------------------------------------------------

#define B_DIM 32
#define L_DIM 512
#define D_DIM 1024
#define NB 128
#define TPB 256

typedef unsigned long long u64;

__device__ unsigned g_ctrs[4];

__global__ void init_flags_kernel() {
    if (threadIdx.x < 4) g_ctrs[threadIdx.x] = 0u;
}

__device__ __forceinline__ u64 pack2(float lo, float hi) {
    u64 r;
    asm("mov.b64 %0, {%1, %2};" : "=l"(r) : "f"(lo), "f"(hi));
    return r;
}
__device__ __forceinline__ void unpack2(u64 v, float& lo, float& hi) {
    asm("mov.b64 {%0, %1}, %2;" : "=f"(lo), "=f"(hi) : "l"(v));
}
__device__ __forceinline__ void ffma2(u64& d, u64 a, u64 b) {
    asm("fma.rn.f32x2 %0, %1, %2, %0;" : "+l"(d) : "l"(a), "l"(b));
}

// tf32 split: hi = tf32(v), lo = tf32(v - float(hi))
__device__ __forceinline__ void tf32_split(float v, uint32_t& hi, uint32_t& lo) {
    asm("cvt.rna.tf32.f32 %0, %1;" : "=r"(hi) : "f"(v));
    float r = v - __uint_as_float(hi);
    asm("cvt.rna.tf32.f32 %0, %1;" : "=r"(lo) : "f"(r));
}

__device__ __forceinline__ void mma_tf32(float* d, const uint32_t* a, const uint32_t* b) {
    asm("mma.sync.aligned.m16n8k8.row.col.f32.tf32.tf32.f32 "
        "{%0,%1,%2,%3}, {%4,%5,%6,%7}, {%8,%9}, {%0,%1,%2,%3};"
        : "+f"(d[0]), "+f"(d[1]), "+f"(d[2]), "+f"(d[3])
        : "r"(a[0]), "r"(a[1]), "r"(a[2]), "r"(a[3]), "r"(b[0]), "r"(b[1]));
}

__device__ __forceinline__ uint32_t smem_u32p(const void* p) {
    uint32_t a;
    asm("{ .reg .u64 t; cvta.to.shared.u64 t, %1; cvt.u32.u64 %0, t; }" : "=r"(a) : "l"(p));
    return a;
}
__device__ __forceinline__ void cp16(uint32_t dst, const void* src) {
    asm volatile("cp.async.cg.shared.global [%0], [%1], 16;" :: "r"(dst), "l"(src));
}

// ---------------------------------------------------------------------------
// Phase 1: C[16384,1024] = A[16384,1024] * W[1024,1024], 3xTF32 mma.sync.
// Block tile 128x128, 8 warps (2 x 4), warp tile 64x32, K-tile 32.
// A in SMEM [m][k] stride 36 (bank 4*lr+lc, conflict-free).
// B in SMEM [k][n] stride 136 (bank 8*lc+lr, conflict-free), cp.async-able.
// Double-buffered via cp.async groups.
// ---------------------------------------------------------------------------
#define KT 32
#define AST 36
#define BST 136
#define ABUF_F (128 * AST)               // 4608 floats
#define BBUF_F (KT * BST)                // 4352 floats
#define P1_SMEM_BYTES ((2 * ABUF_F + 2 * BBUF_F) * 4)

__global__ __launch_bounds__(256, 2) void gemm_mma_kernel(
    const float* __restrict__ A, const float* __restrict__ W,
    float* __restrict__ C)
{
    extern __shared__ __align__(16) float sm1[];
    float* As = sm1;                     // [2][128*AST]
    float* Bs = sm1 + 2 * ABUF_F;        // [2][KT*BST]

    const int tid  = threadIdx.x;
    const int warp = tid >> 5;
    const int lane = tid & 31;
    const int wm = warp >> 2;        // 0..1  -> m offset wm*64
    const int wn = warp & 3;         // 0..3  -> n offset wn*32
    const int m0 = blockIdx.y * 128;
    const int n0 = blockIdx.x * 128;

    const int lr = lane >> 2;        // 0..7
    const int lc = lane & 3;         // 0..3

    // staging decomposition (per thread, 4 chunks each for A and B)
    const int ar = tid >> 1;                   // base pattern via idx below
    (void)ar;

    const uint32_t asb[2] = { smem_u32p(As), smem_u32p(As + ABUF_F) };
    const uint32_t bsb[2] = { smem_u32p(Bs), smem_u32p(Bs + BBUF_F) };

    float acc[4][4][4];
#pragma unroll
    for (int i = 0; i < 4; ++i)
#pragma unroll
        for (int j = 0; j < 4; ++j)
#pragma unroll
            for (int p = 0; p < 4; ++p) acc[i][j][p] = 0.0f;

    auto issue_tile = [&](int buf, int k0) {
#pragma unroll
        for (int it = 0; it < 4; ++it) {
            int idx = it * 256 + tid;          // 0..1023
            int r = idx >> 3, k4 = idx & 7;    // A: 128 rows x 8 chunks
            cp16(asb[buf] + (uint32_t)(r * AST + k4 * 4) * 4,
                 A + (size_t)(m0 + r) * D_DIM + k0 + k4 * 4);
        }
#pragma unroll
        for (int it = 0; it < 4; ++it) {
            int idx = it * 256 + tid;
            int kr = idx >> 5, n4 = idx & 31;  // B: 32 rows x 32 chunks
            cp16(bsb[buf] + (uint32_t)(kr * BST + n4 * 4) * 4,
                 W + (size_t)(k0 + kr) * D_DIM + n0 + n4 * 4);
        }
        asm volatile("cp.async.commit_group;");
    };

    // prologue: tile 0 into buffer 0
    issue_tile(0, 0);

    int cur = 0;
    for (int kt = 0; kt < D_DIM / KT; ++kt) {
        const bool more = (kt + 1) < (D_DIM / KT);
        if (more) {
            issue_tile(cur ^ 1, (kt + 1) * KT);
            asm volatile("cp.async.wait_group 1;");
        } else {
            asm volatile("cp.async.wait_group 0;");
        }
        __syncthreads();

        const float* as = As + cur * ABUF_F;
        const float* bs = Bs + cur * BBUF_F;
#pragma unroll
        for (int ks = 0; ks < 4; ++ks) {
            const int kbase = ks * 8;
            uint32_t ah[4][4], al[4][4];
#pragma unroll
            for (int fm = 0; fm < 4; ++fm) {
                const int rbase = wm * 64 + fm * 16;
                float a0 = as[(rbase + lr) * AST + kbase + lc];
                float a1 = as[(rbase + lr + 8) * AST + kbase + lc];
                float a2 = as[(rbase + lr) * AST + kbase + lc + 4];
                float a3 = as[(rbase + lr + 8) * AST + kbase + lc + 4];
                tf32_split(a0, ah[fm][0], al[fm][0]);
                tf32_split(a1, ah[fm][1], al[fm][1]);
                tf32_split(a2, ah[fm][2], al[fm][2]);
                tf32_split(a3, ah[fm][3], al[fm][3]);
            }
            uint32_t bh[4][2], bl[4][2];
#pragma unroll
            for (int fn = 0; fn < 4; ++fn) {
                const int nbase = wn * 32 + fn * 8;
                float b0 = bs[(kbase + lc) * BST + nbase + lr];
                float b1 = bs[(kbase + lc + 4) * BST + nbase + lr];
                tf32_split(b0, bh[fn][0], bl[fn][0]);
                tf32_split(b1, bh[fn][1], bl[fn][1]);
            }
#pragma unroll
            for (int fm = 0; fm < 4; ++fm)
#pragma unroll
                for (int fn = 0; fn < 4; ++fn) {
                    mma_tf32(acc[fm][fn], ah[fm], bl[fn]);
                    mma_tf32(acc[fm][fn], al[fm], bh[fn]);
                    mma_tf32(acc[fm][fn], ah[fm], bh[fn]);
                }
        }
        __syncthreads();   // computing done before next issue overwrites cur
        cur ^= 1;
    }

    // epilogue: store accumulators (float2 per frag-row)
#pragma unroll
    for (int fm = 0; fm < 4; ++fm) {
        const int rbase = m0 + wm * 64 + fm * 16 + lr;
#pragma unroll
        for (int fn = 0; fn < 4; ++fn) {
            const int cbase = n0 + wn * 32 + fn * 8 + lc * 2;
            *(float2*)(C + (size_t)rbase * D_DIM + cbase) =
                make_float2(acc[fm][fn][0], acc[fm][fn][1]);
            *(float2*)(C + (size_t)(rbase + 8) * D_DIM + cbase) =
                make_float2(acc[fm][fn][2], acc[fm][fn][3]);
        }
    }
}

// ---------------------------------------------------------------------------
// Phase 2: persistent recurrence (R11 version, 256 threads).
// bid -> (bq = bid>>5 owns b in [bq*8, bq*8+8), jg = bid&31 owns 32 columns).
// Thread: jq = lane&7 -> 4 columns; kc = warp*4 + (lane>>3) -> 32 k.
// Partial STS column-swizzled (kc ^ (jq<<2)) -> conflict-free.
// ---------------------------------------------------------------------------
#define HROW_F 1152
#define PART_STRIDE 36
#define HS_FLOATS (8 * HROW_F)
#define PART_OFF HS_FLOATS
#define PART_FLOATS (8 * 32 * PART_STRIDE)
#define SMEM2_FLOATS (PART_OFF + PART_FLOATS)

__global__ __launch_bounds__(TPB, 1) void rnn_steps_kernel(
    float* __restrict__ out,          // [B, L, D]: holds xp, overwritten by h
    const float* __restrict__ h0,     // [B, D]
    const float* __restrict__ Wh)     // [D, D]
{
    extern __shared__ __align__(16) float smem[];
    float* hs   = smem;
    float* part = smem + PART_OFF;

    const int tid  = threadIdx.x;
    const int warp = tid >> 5;
    const int lane = tid & 31;
    const int bid  = blockIdx.x;
    const int jg = bid & 31, bq = bid >> 5;
    const int j0 = jg * 32, b0 = bq * 8;
    const int jq = lane & 7;
    const int kc = (warp << 2) | (lane >> 3);
    const int kb = kc * 32;
    const int kcs = kc ^ (jq << 2);            // swizzled partial column

    u64 wreg[4][16];
#pragma unroll
    for (int jl = 0; jl < 4; ++jl) {
        const int jcol = j0 + jq * 4 + jl;
#pragma unroll
        for (int kk = 0; kk < 16; ++kk) {
            float w0 = Wh[(size_t)(kb + 2 * kk)     * D_DIM + jcol];
            float w1 = Wh[(size_t)(kb + 2 * kk + 1) * D_DIM + jcol];
            wreg[jl][kk] = pack2(w0, w1);
        }
    }

    unsigned* ctr = &g_ctrs[bq];
    const size_t obase = ((size_t)(b0 + warp) * L_DIM) * D_DIM + j0 + lane;

    float xp = out[obase];

    for (int t = 0; t < L_DIM; ++t) {
        const size_t orow = obase + (size_t)t * D_DIM;

        const float* src = (t == 0)
            ? (h0 + (size_t)(b0 + warp) * D_DIM)
            : (out + ((size_t)(b0 + warp) * L_DIM + (t - 1)) * D_DIM);
#pragma unroll
        for (int half = 0; half < 2; ++half) {
            float4 v[4];
#pragma unroll
            for (int m = 0; m < 4; ++m)
                v[m] = __ldcg((const float4*)(src + ((half * 4 + m) * 32 + lane) * 4));
#pragma unroll
            for (int m = 0; m < 4; ++m) {
                int idx = (half * 4 + m) * 32 + lane;
                *(float4*)(hs + warp * HROW_F + (idx >> 3) * 36 + (idx & 7) * 4) = v[m];
            }
        }
        __syncthreads();

        // early xp prefetch for t+1: slot written only by this thread at t+1.
        float xp_next = 0.0f;
        if (t + 1 < L_DIM) xp_next = out[orow + D_DIM];

        u64 acc[8][4];
#pragma unroll
        for (int b = 0; b < 8; ++b)
#pragma unroll
            for (int jl = 0; jl < 4; ++jl) acc[b][jl] = 0ull;

#pragma unroll
        for (int b = 0; b < 8; ++b) {
            const ulonglong2* hb = (const ulonglong2*)(hs + b * HROW_F + kc * 36);
#pragma unroll
            for (int i = 0; i < 8; ++i) {
                ulonglong2 hp = hb[i];
                ffma2(acc[b][0], hp.x, wreg[0][2 * i]);
                ffma2(acc[b][1], hp.x, wreg[1][2 * i]);
                ffma2(acc[b][2], hp.x, wreg[2][2 * i]);
                ffma2(acc[b][3], hp.x, wreg[3][2 * i]);
                ffma2(acc[b][0], hp.y, wreg[0][2 * i + 1]);
                ffma2(acc[b][1], hp.y, wreg[1][2 * i + 1]);
                ffma2(acc[b][2], hp.y, wreg[2][2 * i + 1]);
                ffma2(acc[b][3], hp.y, wreg[3][2 * i + 1]);
            }
        }

#pragma unroll
        for (int b = 0; b < 8; ++b)
#pragma unroll
            for (int jl = 0; jl < 4; ++jl) {
                float lo, hi;
                unpack2(acc[b][jl], lo, hi);
                part[(b * 32 + jq * 4 + jl) * PART_STRIDE + kcs] = lo + hi;
            }

        __syncthreads();

        float s = xp;
        const float* pr = part + (warp * 32 + lane) * PART_STRIDE;
#pragma unroll
        for (int g = 0; g < 8; ++g) {
            float4 p = *(const float4*)(pr + g * 4);
            s += (p.x + p.y) + (p.z + p.w);
        }
        out[orow] = tanhf(s);

        if (t + 1 < L_DIM) {
            __syncthreads();
            if (tid == 0) {
                asm volatile("red.release.gpu.add.u32 [%0], 1;" :: "l"(ctr) : "memory");
                const unsigned target = 32u * (unsigned)(t + 1);
                unsigned v;
                int spins = 0;
                while (true) {
                    asm volatile("ld.acquire.gpu.u32 %0, [%1];" : "=r"(v) : "l"(ctr) : "memory");
                    if (v >= target) break;
                    if (++spins > 2) __nanosleep(32);
                }
            }
            __syncthreads();
        }

        xp = xp_next;
    }
}

// ---------------------------------------------------------------------------
extern "C" void kernel_launch(void* const* d_in, const int* in_sizes, int n_in,
                              void* d_out, int out_size)
{
    (void)in_sizes; (void)n_in; (void)out_size;
    const float* x  = (const float*)d_in[0];
    const float* h0 = (const float*)d_in[1];
    const float* Wx = (const float*)d_in[2];
    const float* Wh = (const float*)d_in[3];
    float* out = (float*)d_out;

    // phase 1: 3xTF32 tensor-core GEMM (cp.async, 2 CTAs/SM)
    cudaFuncSetAttribute(gemm_mma_kernel,
                         cudaFuncAttributeMaxDynamicSharedMemorySize,
                         P1_SMEM_BYTES);
    dim3 g1(D_DIM / 128, (B_DIM * L_DIM) / 128);
    gemm_mma_kernel<<<g1, 256, P1_SMEM_BYTES>>>(x, Wx, out);

    // phase 2: persistent recurrence
    init_flags_kernel<<<1, 32>>>();
    size_t smem_bytes = (size_t)SMEM2_FLOATS * sizeof(float);
    cudaFuncSetAttribute(rnn_steps_kernel,
                         cudaFuncAttributeMaxDynamicSharedMemorySize,
                         (int)smem_bytes);
    rnn_steps_kernel<<<NB, TPB, smem_bytes>>>(out, h0, Wh);
}